// round 13
// baseline (speedup 1.0000x reference)
#include <cuda_runtime.h>
#include <stdint.h>

// FullMultiEmbedding fused single-pass (zero-everything + overwrite hits):
//   out[b, e, :] = weight[e, :] * psw[i]  if e == input_[i] for some i in bag b
//                = 0                       otherwise
// Output [B, NUM_EMB, 64] fp32, 655 MB -> HBM-write-bound.
//
// Inputs (JAX x64 disabled -> "int64" arrays are int32 on the wire):
//   d_in[0] input_             int32   [L]   (12800)
//   d_in[1] offsets            int32   [B]   (256)
//   d_in[2] per_sample_weights float32 [L]
//   d_in[3] weight             float32 [NUM_EMB, 64]
//
// Phase 1 per block: branch-free memset of the whole slice (the hot 99.5%).
// Phase 2 (after __syncthreads): overwrite hit rows. Fast path exploits the
// verified consecutive-run structure of each bag ((start+j) % N); fallback
// scatters the raw index list with last-match-wins.

static constexpr int D4      = 16;   // 64 floats = 16 float4 per row
static constexpr int SPLITS  = 18;   // 256 bags * 18 = 4608 blocks
static constexpr int THREADS = 256;
static constexpr int CAP     = 2048;

__global__ void __launch_bounds__(THREADS) fused_kernel(
        const int* __restrict__ input_,
        const int* __restrict__ offsets,
        const float* __restrict__ psw,
        const float4* __restrict__ weight,
        float4* __restrict__ out,
        int L, int B, int num_emb, int rows_per_slice) {
    __shared__ int   e_list[CAP];
    __shared__ float w_list[CAP];
    __shared__ int   s_consec;

    const int bag   = blockIdx.x / SPLITS;
    const int slice = blockIdx.x % SPLITS;

    const int off = offsets[bag];
    const int end = (bag + 1 < B) ? offsets[bag + 1] : L;
    const int len = end - off;
    const int start = (len > 0) ? input_[off] : 0;
    const bool cache = (len <= CAP);

    if (threadIdx.x == 0) s_consec = 1;
    __syncthreads();
    for (int j = threadIdx.x; j < len; j += THREADS) {
        int e = input_[off + j];
        if (cache) { e_list[j] = e; w_list[j] = psw[off + j]; }
        int expect = start + j;
        if (expect >= num_emb) expect -= num_emb;
        if (e != expect) s_consec = 0;
    }
    __syncthreads();
    const bool consec = (s_consec != 0) && cache && (len <= num_emb);

    const int e0 = slice * rows_per_slice;
    const int e1 = min(e0 + rows_per_slice, num_emb);
    if (e0 >= e1) return;

    float4* __restrict__ bag_base = out + (unsigned)(bag * num_emb) * D4;

    // ---- Phase 1: branch-free memset of the entire slice ----
    {
        float4* __restrict__ base = bag_base + ((unsigned)e0 << 4);
        const int n4 = (e1 - e0) << 4;
        const float4 z = make_float4(0.f, 0.f, 0.f, 0.f);
        #pragma unroll 8
        for (int i = threadIdx.x; i < n4; i += THREADS) base[i] = z;
    }
    __syncthreads();   // order: zeros before hit overwrites (block-scope fence)

    // ---- Phase 2: overwrite hit rows ----
    if (consec) {
        // Hit band [start, start+len) mod N -> <=2 intervals clipped to [e0,e1)
        // Interval A (wrapped part): rows [e0, wa_hi), d = row - start + N
        // Interval B (main part):    rows [b_lo, b_hi), d = row - start
        const int wrap_end = start + len - num_emb;            // may be <= 0
        const int wa_hi = min(e1, max(wrap_end, e0));
        const int b_lo  = max(e0, start);
        const int b_hi  = min(e1, min(start + len, num_emb));

        // Interval A
        {
            const int m4 = (wa_hi - e0) << 4;
            const int dbase = e0 - start + num_emb;
            for (int i = threadIdx.x; i < m4; i += THREADS) {
                int rr = i >> 4, lane = i & 15;
                int row = e0 + rr;
                float w = w_list[dbase + rr];
                float4 v = weight[(unsigned)row * D4 + lane];
                v.x *= w; v.y *= w; v.z *= w; v.w *= w;
                bag_base[((unsigned)row << 4) + lane] = v;
            }
        }
        // Interval B
        if (b_lo < b_hi) {
            const int m4 = (b_hi - b_lo) << 4;
            const int dbase = b_lo - start;
            for (int i = threadIdx.x; i < m4; i += THREADS) {
                int rr = i >> 4, lane = i & 15;
                int row = b_lo + rr;
                float w = w_list[dbase + rr];
                float4 v = weight[(unsigned)row * D4 + lane];
                v.x *= w; v.y *= w; v.z *= w; v.w *= w;
                bag_base[((unsigned)row << 4) + lane] = v;
            }
        }
    } else {
        // General fallback: scatter the bag's index list (last match wins).
        for (int t = threadIdx.x; t < (len << 4); t += THREADS) {
            int j = t >> 4, lane = t & 15;
            int e = cache ? e_list[j] : input_[off + j];
            if (e < e0 || e >= e1) continue;
            // last-wins: skip if a later entry repeats this index
            bool dup = false;
            for (int j2 = j + 1; j2 < len && !dup; j2++) {
                int e2 = cache ? e_list[j2] : input_[off + j2];
                dup = (e2 == e);
            }
            if (dup) continue;
            float w = cache ? w_list[j] : psw[off + j];
            float4 v = weight[(unsigned)e * D4 + lane];
            v.x *= w; v.y *= w; v.z *= w; v.w *= w;
            bag_base[((unsigned)e << 4) + lane] = v;
        }
    }
}

extern "C" void kernel_launch(void* const* d_in, const int* in_sizes, int n_in,
                              void* d_out, int out_size) {
    const int*   input_  = (const int*)d_in[0];
    const int*   offsets = (const int*)d_in[1];
    const float* psw     = (const float*)d_in[2];
    const float* weight  = (const float*)d_in[3];
    float* out = (float*)d_out;

    const int L = in_sizes[0];
    const int B = in_sizes[1];
    const int num_emb = in_sizes[3] / 64;

    const int rows_per_slice = (num_emb + SPLITS - 1) / SPLITS;
    const int blocks = B * SPLITS;

    fused_kernel<<<blocks, THREADS>>>(input_, offsets, psw,
                                      (const float4*)weight,
                                      (float4*)out,
                                      L, B, num_emb, rows_per_slice);
}

// round 14
// speedup vs baseline: 1.0667x; 1.0667x over previous
#include <cuda_runtime.h>
#include <stdint.h>

// FullMultiEmbedding fused single-pass (zero-everything + overwrite hits):
//   out[b, e, :] = weight[e, :] * psw[i]  if e == input_[i] for some i in bag b
//                = 0                       otherwise
// Output [B, NUM_EMB, 64] fp32, 655 MB -> HBM-write-bound.
//
// Inputs (JAX x64 disabled -> "int64" arrays are int32 on the wire):
//   d_in[0] input_             int32   [L]   (12800)
//   d_in[1] offsets            int32   [B]   (256)
//   d_in[2] per_sample_weights float32 [L]
//   d_in[3] weight             float32 [NUM_EMB, 64]
//
// Grid: 256 bags x SPLITS=37 slices = 9472 blocks = 148 SMs x 64 exactly
// (perfect wave quantization; uniform block durations).
// Phase 1: branch-free streaming memset of the slice. Phase 2: overwrite the
// <=2 contiguous hit-row intervals (bag indices form a verified consecutive
// run (start+j) % N); fallback scatters the raw list (last match wins).

static constexpr int D4      = 16;   // 64 floats = 16 float4 per row
static constexpr int SPLITS  = 37;   // 256*37 = 9472 = 148*64
static constexpr int THREADS = 256;
static constexpr int CAP     = 2048;

__device__ __forceinline__ void st_cs(float4* p, float4 v) {
    asm volatile("st.global.cs.v4.f32 [%0], {%1,%2,%3,%4};"
                 :: "l"(p), "f"(v.x), "f"(v.y), "f"(v.z), "f"(v.w) : "memory");
}

__global__ void __launch_bounds__(THREADS) fused_kernel(
        const int* __restrict__ input_,
        const int* __restrict__ offsets,
        const float* __restrict__ psw,
        const float4* __restrict__ weight,
        float4* __restrict__ out,
        int L, int B, int num_emb, int rows_per_slice) {
    __shared__ int   e_list[CAP];
    __shared__ float w_list[CAP];
    __shared__ int   s_consec;

    const int bag   = blockIdx.x / SPLITS;
    const int slice = blockIdx.x % SPLITS;

    const int off = offsets[bag];
    const int end = (bag + 1 < B) ? offsets[bag + 1] : L;
    const int len = end - off;
    const int start = (len > 0) ? input_[off] : 0;
    const bool cache = (len <= CAP);

    if (threadIdx.x == 0) s_consec = 1;
    __syncthreads();
    for (int j = threadIdx.x; j < len; j += THREADS) {
        int e = input_[off + j];
        if (cache) { e_list[j] = e; w_list[j] = psw[off + j]; }
        int expect = start + j;
        if (expect >= num_emb) expect -= num_emb;
        if (e != expect) s_consec = 0;
    }
    __syncthreads();
    const bool consec = (s_consec != 0) && cache && (len <= num_emb);

    const int e0 = slice * rows_per_slice;
    const int e1 = min(e0 + rows_per_slice, num_emb);
    if (e0 >= e1) return;

    float4* __restrict__ bag_base = out + (unsigned)(bag * num_emb) * D4;

    // ---- Phase 1: branch-free streaming memset of the entire slice ----
    {
        float4* __restrict__ base = bag_base + ((unsigned)e0 << 4);
        const int n4 = (e1 - e0) << 4;
        const float4 z = make_float4(0.f, 0.f, 0.f, 0.f);
        #pragma unroll 8
        for (int i = threadIdx.x; i < n4; i += THREADS) st_cs(base + i, z);
    }
    __syncthreads();   // order zeros before hit overwrites (block-scope fence)

    // ---- Phase 2: overwrite hit rows ----
    if (consec) {
        // Hit band [start, start+len) mod N -> <=2 intervals clipped to [e0,e1)
        const int wrap_end = start + len - num_emb;            // may be <= 0
        const int wa_hi = min(e1, max(wrap_end, e0));          // wrapped part
        const int b_lo  = max(e0, start);                      // main part
        const int b_hi  = min(e1, min(start + len, num_emb));

        // Interval A (wrapped): rows [e0, wa_hi), d = row - start + N
        {
            const int m4 = (wa_hi - e0) << 4;
            const int dbase = e0 - start + num_emb;
            for (int i = threadIdx.x; i < m4; i += THREADS) {
                int rr = i >> 4, lane = i & 15;
                int row = e0 + rr;
                float w = w_list[dbase + rr];
                float4 v = weight[(unsigned)row * D4 + lane];
                v.x *= w; v.y *= w; v.z *= w; v.w *= w;
                st_cs(&bag_base[((unsigned)row << 4) + lane], v);
            }
        }
        // Interval B (main): rows [b_lo, b_hi), d = row - start
        if (b_lo < b_hi) {
            const int m4 = (b_hi - b_lo) << 4;
            const int dbase = b_lo - start;
            for (int i = threadIdx.x; i < m4; i += THREADS) {
                int rr = i >> 4, lane = i & 15;
                int row = b_lo + rr;
                float w = w_list[dbase + rr];
                float4 v = weight[(unsigned)row * D4 + lane];
                v.x *= w; v.y *= w; v.z *= w; v.w *= w;
                st_cs(&bag_base[((unsigned)row << 4) + lane], v);
            }
        }
    } else {
        // General fallback: scatter the bag's index list (last match wins).
        for (int t = threadIdx.x; t < (len << 4); t += THREADS) {
            int j = t >> 4, lane = t & 15;
            int e = cache ? e_list[j] : input_[off + j];
            if (e < e0 || e >= e1) continue;
            bool dup = false;
            for (int j2 = j + 1; j2 < len && !dup; j2++) {
                int e2 = cache ? e_list[j2] : input_[off + j2];
                dup = (e2 == e);
            }
            if (dup) continue;
            float w = cache ? w_list[j] : psw[off + j];
            float4 v = weight[(unsigned)e * D4 + lane];
            v.x *= w; v.y *= w; v.z *= w; v.w *= w;
            bag_base[((unsigned)e << 4) + lane] = v;
        }
    }
}

extern "C" void kernel_launch(void* const* d_in, const int* in_sizes, int n_in,
                              void* d_out, int out_size) {
    const int*   input_  = (const int*)d_in[0];
    const int*   offsets = (const int*)d_in[1];
    const float* psw     = (const float*)d_in[2];
    const float* weight  = (const float*)d_in[3];
    float* out = (float*)d_out;

    const int L = in_sizes[0];
    const int B = in_sizes[1];
    const int num_emb = in_sizes[3] / 64;

    const int rows_per_slice = (num_emb + SPLITS - 1) / SPLITS;
    const int blocks = B * SPLITS;

    fused_kernel<<<blocks, THREADS>>>(input_, offsets, psw,
                                      (const float4*)weight,
                                      (float4*)out,
                                      L, B, num_emb, rows_per_slice);
}

// round 16
// speedup vs baseline: 1.0715x; 1.0045x over previous
#include <cuda_runtime.h>
#include <stdint.h>

// FullMultiEmbedding fused single-pass (memset-first + overwrite hits):
//   out[b, e, :] = weight[e, :] * psw[i]  if e == input_[i] for some i in bag b
//                = 0                       otherwise
// Output [B, NUM_EMB, 64] fp32, 655 MB -> HBM-write-bound (~7 TB/s wall).
//
// Inputs (JAX x64 disabled -> "int64" arrays are int32 on the wire):
//   d_in[0] input_             int32   [L]   (12800)
//   d_in[1] offsets            int32   [B]   (256)
//   d_in[2] per_sample_weights float32 [L]
//   d_in[3] weight             float32 [NUM_EMB, 64]
//
// Grid: 256 bags x SPLITS=37 = 9472 blocks = 148 SMs x 64 (perfect waves).
// Phase 1 (no loads, no barriers): streaming memset of the slice — stores
// start within ~20 cycles of block launch. Phase 2: load + verify the bag's
// index list (overlaps with store drain), then overwrite the <=2 contiguous
// hit-row intervals (bag indices form a consecutive run (start+j) % N);
// fallback scatters the raw list with last-match-wins.

static constexpr int D4      = 16;   // 64 floats = 16 float4 per row
static constexpr int SPLITS  = 37;   // 256*37 = 9472 = 148*64
static constexpr int THREADS = 256;
static constexpr int CAP     = 2048;

__device__ __forceinline__ void st_cs(float4* p, float4 v) {
    asm volatile("st.global.cs.v4.f32 [%0], {%1,%2,%3,%4};"
                 :: "l"(p), "f"(v.x), "f"(v.y), "f"(v.z), "f"(v.w) : "memory");
}

__global__ void __launch_bounds__(THREADS) fused_kernel(
        const int* __restrict__ input_,
        const int* __restrict__ offsets,
        const float* __restrict__ psw,
        const float4* __restrict__ weight,
        float4* __restrict__ out,
        int L, int B, int num_emb, int rows_per_slice) {
    __shared__ int   e_list[CAP];
    __shared__ float w_list[CAP];
    __shared__ int   s_consec;

    const int bag   = blockIdx.x / SPLITS;
    const int slice = blockIdx.x - bag * SPLITS;

    const int e0 = slice * rows_per_slice;
    const int e1 = min(e0 + rows_per_slice, num_emb);
    if (e0 >= e1) return;

    float4* __restrict__ bag_base = out + (unsigned)(bag * num_emb) * D4;

    // ---- Phase 1: streaming memset, issued before ANY load/barrier ----
    {
        float4* __restrict__ base = bag_base + ((unsigned)e0 << 4);
        const int n4 = (e1 - e0) << 4;
        const float4 z = make_float4(0.f, 0.f, 0.f, 0.f);
        #pragma unroll 8
        for (int i = threadIdx.x; i < n4; i += THREADS) st_cs(base + i, z);
    }

    // ---- Load + verify bag metadata (overlaps with store drain) ----
    const int off = offsets[bag];
    const int end = (bag + 1 < B) ? offsets[bag + 1] : L;
    const int len = end - off;
    const int start = (len > 0) ? input_[off] : 0;
    const bool cache = (len <= CAP);

    if (threadIdx.x == 0) s_consec = 1;
    __syncthreads();
    for (int j = threadIdx.x; j < len; j += THREADS) {
        int e = input_[off + j];
        if (cache) { e_list[j] = e; w_list[j] = psw[off + j]; }
        int expect = start + j;
        if (expect >= num_emb) expect -= num_emb;
        if (e != expect) s_consec = 0;
    }
    __syncthreads();   // also orders phase-1 zeros before phase-2 overwrites
    const bool consec = (s_consec != 0) && cache && (len <= num_emb);

    // ---- Phase 2: overwrite hit rows ----
    if (consec) {
        // Hit band [start, start+len) mod N -> <=2 intervals clipped to [e0,e1)
        const int wrap_end = start + len - num_emb;            // may be <= 0
        const int wa_hi = min(e1, max(wrap_end, e0));          // wrapped part
        const int b_lo  = max(e0, start);                      // main part
        const int b_hi  = min(e1, min(start + len, num_emb));

        // Interval A (wrapped): rows [e0, wa_hi), d = row - start + N
        {
            const int m4 = (wa_hi - e0) << 4;
            const int dbase = e0 - start + num_emb;
            for (int i = threadIdx.x; i < m4; i += THREADS) {
                int rr = i >> 4, lane = i & 15;
                int row = e0 + rr;
                float w = w_list[dbase + rr];
                float4 v = weight[(unsigned)row * D4 + lane];
                v.x *= w; v.y *= w; v.z *= w; v.w *= w;
                st_cs(&bag_base[((unsigned)row << 4) + lane], v);
            }
        }
        // Interval B (main): rows [b_lo, b_hi), d = row - start
        if (b_lo < b_hi) {
            const int m4 = (b_hi - b_lo) << 4;
            const int dbase = b_lo - start;
            for (int i = threadIdx.x; i < m4; i += THREADS) {
                int rr = i >> 4, lane = i & 15;
                int row = b_lo + rr;
                float w = w_list[dbase + rr];
                float4 v = weight[(unsigned)row * D4 + lane];
                v.x *= w; v.y *= w; v.z *= w; v.w *= w;
                st_cs(&bag_base[((unsigned)row << 4) + lane], v);
            }
        }
    } else {
        // General fallback: scatter the bag's index list (last match wins).
        for (int t = threadIdx.x; t < (len << 4); t += THREADS) {
            int j = t >> 4, lane = t & 15;
            int e = cache ? e_list[j] : input_[off + j];
            if (e < e0 || e >= e1) continue;
            bool dup = false;
            for (int j2 = j + 1; j2 < len && !dup; j2++) {
                int e2 = cache ? e_list[j2] : input_[off + j2];
                dup = (e2 == e);
            }
            if (dup) continue;
            float w = cache ? w_list[j] : psw[off + j];
            float4 v = weight[(unsigned)e * D4 + lane];
            v.x *= w; v.y *= w; v.z *= w; v.w *= w;
            bag_base[((unsigned)e << 4) + lane] = v;
        }
    }
}

extern "C" void kernel_launch(void* const* d_in, const int* in_sizes, int n_in,
                              void* d_out, int out_size) {
    const int*   input_  = (const int*)d_in[0];
    const int*   offsets = (const int*)d_in[1];
    const float* psw     = (const float*)d_in[2];
    const float* weight  = (const float*)d_in[3];
    float* out = (float*)d_out;

    const int L = in_sizes[0];
    const int B = in_sizes[1];
    const int num_emb = in_sizes[3] / 64;

    const int rows_per_slice = (num_emb + SPLITS - 1) / SPLITS;
    const int blocks = B * SPLITS;

    fused_kernel<<<blocks, THREADS>>>(input_, offsets, psw,
                                      (const float4*)weight,
                                      (float4*)out,
                                      L, B, num_emb, rows_per_slice);
}